// round 4
// baseline (speedup 1.0000x reference)
#include <cuda_runtime.h>
#include <cuda_bf16.h>
#include <cstdint>

// Problem dims
#define BATCH 4
#define SEQ   2048
#define DIM   1024
#define MROWS (BATCH * SEQ)   // 8192

// ===========================================================================
// Scratch (device globals; no allocation allowed anywhere)
// ===========================================================================
__device__ __align__(16) __nv_bfloat16 g_xh[(size_t)MROWS * DIM];
__device__ __align__(16) __nv_bfloat16 g_xl[(size_t)MROWS * DIM];
__device__ __align__(16) __nv_bfloat16 g_wth[(size_t)3 * DIM * DIM];  // W^T hi [n][k]
__device__ __align__(16) __nv_bfloat16 g_wtl[(size_t)3 * DIM * DIM];  // W^T lo
__device__ __align__(16) __nv_bfloat16 g_qh[(size_t)MROWS * DIM];
__device__ __align__(16) __nv_bfloat16 g_ql[(size_t)MROWS * DIM];
__device__ __align__(16) __nv_bfloat16 g_kh[(size_t)MROWS * DIM];
__device__ __align__(16) __nv_bfloat16 g_kl[(size_t)MROWS * DIM];
__device__ __align__(16) __nv_bfloat16 g_vh[(size_t)MROWS * DIM];
__device__ __align__(16) __nv_bfloat16 g_vl[(size_t)MROWS * DIM];
__device__ __align__(16) __nv_bfloat16 g_vth[(size_t)MROWS * DIM];   // V^T per batch [D][S]
__device__ __align__(16) __nv_bfloat16 g_vtl[(size_t)MROWS * DIM];
__device__ __align__(16) float         g_s[(size_t)BATCH * SEQ * SEQ];
__device__ __align__(16) __nv_bfloat16 g_ph[(size_t)BATCH * SEQ * SEQ];
__device__ __align__(16) __nv_bfloat16 g_pl[(size_t)BATCH * SEQ * SEQ];

// ===========================================================================
// Baseline-ISA warp MMA helpers (sm_80+: mma.sync / ldmatrix / cp.async)
// ===========================================================================
__device__ __forceinline__ uint32_t smem_u32(const void* p) {
    uint32_t a;
    asm("{ .reg .u64 t; cvta.to.shared.u64 t, %1; cvt.u32.u64 %0, t; }" : "=r"(a) : "l"(p));
    return a;
}

__device__ __forceinline__ void ldsm_x4(uint32_t& r0, uint32_t& r1, uint32_t& r2, uint32_t& r3,
                                        uint32_t addr) {
    asm volatile("ldmatrix.sync.aligned.m8n8.x4.shared.b16 {%0,%1,%2,%3}, [%4];"
                 : "=r"(r0), "=r"(r1), "=r"(r2), "=r"(r3) : "r"(addr));
}

__device__ __forceinline__ void mma16816(float* c, const uint32_t* a, const uint32_t* b) {
    asm volatile(
        "mma.sync.aligned.m16n8k16.row.col.f32.bf16.bf16.f32 "
        "{%0,%1,%2,%3}, {%4,%5,%6,%7}, {%8,%9}, {%0,%1,%2,%3};"
        : "+f"(c[0]), "+f"(c[1]), "+f"(c[2]), "+f"(c[3])
        : "r"(a[0]), "r"(a[1]), "r"(a[2]), "r"(a[3]), "r"(b[0]), "r"(b[1]));
}

__device__ __forceinline__ void cp_async16(uint32_t saddr, const void* gaddr) {
    asm volatile("cp.async.cg.shared.global [%0], [%1], 16;" :: "r"(saddr), "l"(gaddr));
}
__device__ __forceinline__ void cp_commit() { asm volatile("cp.async.commit_group;"); }
template <int N> __device__ __forceinline__ void cp_wait() {
    asm volatile("cp.async.wait_group %0;" :: "n"(N));
}

__device__ __forceinline__ uint32_t pack2(__nv_bfloat16 a, __nv_bfloat16 b) {
    __nv_bfloat162 p; p.x = a; p.y = b;
    return *reinterpret_cast<uint32_t*>(&p);
}

// ===========================================================================
// GEMM mainloop: acc[4][4][4] += (Ah+Al)[128,K] @ (Bh+Bl)[128,K]^T  (bf16x3)
//   CTA tile 128x128, K-chunk 16, 256 threads = 8 warps (2 M x 4 N),
//   warp tile 64x32. Smem: 3 stages x 4 tiles x [128 rows x 48B] (32B data+16 pad).
//   3-stage cp.async pipeline, ONE __syncthreads per stage, combo-outer MMAs.
// ===========================================================================
#define ROW_B   48
#define TILE_B  (128 * ROW_B)    // 6144
#define STAGE_B (4 * TILE_B)     // 24576
#define NSTG_BUF 3
#define SMEM_GEMM_BYTES (NSTG_BUF * STAGE_B)  // 73728

// copy one 128x16 bf16 tile (row stride ld elems) into padded smem
// (each of 256 threads copies one 16B chunk: row = t>>1, col16 = t&1)
__device__ __forceinline__ void cpa_tile(const __nv_bfloat16* __restrict__ g, int ld,
                                         uint32_t sdst, int t) {
    const int row = t >> 1;
    const int col = t & 1;
    const char* gp = reinterpret_cast<const char*>(g) + (size_t)row * ld * 2 + col * 16;
    cp_async16(sdst + row * ROW_B + col * 16, gp);
}

__device__ __forceinline__ void load_stage(
    const __nv_bfloat16* Ah, const __nv_bfloat16* Al, int lda,
    const __nv_bfloat16* Bh, const __nv_bfloat16* Bl, int ldb,
    int stg, uint32_t sbase, int buf, int t)
{
    const size_t ko = (size_t)stg * 16;
    const uint32_t st = sbase + buf * STAGE_B;
    cpa_tile(Ah + ko, lda, st + 0 * TILE_B, t);
    cpa_tile(Al + ko, lda, st + 1 * TILE_B, t);
    cpa_tile(Bh + ko, ldb, st + 2 * TILE_B, t);
    cpa_tile(Bl + ko, ldb, st + 3 * TILE_B, t);
    cp_commit();
}

__device__ __forceinline__ void mma_mainloop(
    const __nv_bfloat16* __restrict__ Ah, const __nv_bfloat16* __restrict__ Al, int lda,
    const __nv_bfloat16* __restrict__ Bh, const __nv_bfloat16* __restrict__ Bl, int ldb,
    int Kdim, char* smem, float acc[4][4][4])
{
    const int t    = threadIdx.x;
    const int lane = t & 31;
    const int warp = t >> 5;
    const int wm   = warp & 1;   // 0..1  (64-row block)
    const int wn   = warp >> 1;  // 0..3  (32-col block)
    const uint32_t sbase = smem_u32(smem);

    // ldmatrix per-lane offsets (canonical m16n8k16 mappings)
    const int aRow = lane & 15;
    const int aK   = (lane >> 4) & 1;
    const int bRow = (lane & 7) | (((lane >> 4) & 1) << 3);
    const int bK   = (lane >> 3) & 1;

    const uint32_t aBase = (wm * 64 + aRow) * ROW_B + aK * 16;
    const uint32_t bBase = (wn * 32 + bRow) * ROW_B + bK * 16;

#pragma unroll
    for (int i = 0; i < 4; i++)
#pragma unroll
        for (int j = 0; j < 4; j++)
#pragma unroll
            for (int q = 0; q < 4; q++) acc[i][j][q] = 0.0f;

    const int nstg = Kdim >> 4;
    load_stage(Ah, Al, lda, Bh, Bl, ldb, 0, sbase, 0, t);
    load_stage(Ah, Al, lda, Bh, Bl, ldb, 1, sbase, 1, t);

    int rbuf = 0, wbuf = 2;
    for (int i = 0; i < nstg; i++) {
        if (i + 1 < nstg) cp_wait<1>(); else cp_wait<0>();
        __syncthreads();
        if (i + 2 < nstg) {
            load_stage(Ah, Al, lda, Bh, Bl, ldb, i + 2, sbase, wbuf, t);
            wbuf = (wbuf == 2) ? 0 : wbuf + 1;
        }

        const uint32_t st  = sbase + rbuf * STAGE_B;
        rbuf = (rbuf == 2) ? 0 : rbuf + 1;
        const uint32_t AhT = st, AlT = st + TILE_B, BhT = st + 2 * TILE_B, BlT = st + 3 * TILE_B;

        // Phase 1: load Ah, Bh; 16 independent hh MMAs
        uint32_t ah[4][4], bh[4][2];
#pragma unroll
        for (int mt = 0; mt < 4; mt++)
            ldsm_x4(ah[mt][0], ah[mt][1], ah[mt][2], ah[mt][3], AhT + aBase + mt * 16 * ROW_B);
#pragma unroll
        for (int g = 0; g < 2; g++) {
            uint32_t r0, r1, r2, r3;
            ldsm_x4(r0, r1, r2, r3, BhT + bBase + g * 16 * ROW_B);
            bh[2 * g][0] = r0;     bh[2 * g][1] = r1;
            bh[2 * g + 1][0] = r2; bh[2 * g + 1][1] = r3;
        }
#pragma unroll
        for (int mt = 0; mt < 4; mt++)
#pragma unroll
            for (int nt = 0; nt < 4; nt++) mma16816(acc[mt][nt], ah[mt], bh[nt]);

        // Phase 2: load Bl; 16 independent hl MMAs
        {
            uint32_t bl[4][2];
#pragma unroll
            for (int g = 0; g < 2; g++) {
                uint32_t r0, r1, r2, r3;
                ldsm_x4(r0, r1, r2, r3, BlT + bBase + g * 16 * ROW_B);
                bl[2 * g][0] = r0;     bl[2 * g][1] = r1;
                bl[2 * g + 1][0] = r2; bl[2 * g + 1][1] = r3;
            }
#pragma unroll
            for (int mt = 0; mt < 4; mt++)
#pragma unroll
                for (int nt = 0; nt < 4; nt++) mma16816(acc[mt][nt], ah[mt], bl[nt]);
        }

        // Phase 3: load Al; 16 independent lh MMAs
        {
            uint32_t al[4][4];
#pragma unroll
            for (int mt = 0; mt < 4; mt++)
                ldsm_x4(al[mt][0], al[mt][1], al[mt][2], al[mt][3], AlT + aBase + mt * 16 * ROW_B);
#pragma unroll
            for (int mt = 0; mt < 4; mt++)
#pragma unroll
                for (int nt = 0; nt < 4; nt++) mma16816(acc[mt][nt], al[mt], bh[nt]);
        }
    }
    __syncthreads();
}

// acc element coords: tile (mt,nt): r = wm*64 + mt*16 + lane/4 (+8 for c2,c3)
//                     c = wn*32 + nt*8 + (lane%4)*2 (+1 for odd)
// ===========================================================================
// GEMM kernels
// ===========================================================================
__global__ void __launch_bounds__(256, 2) qkv_tc(
    const float* __restrict__ bq, const float* __restrict__ bk, const float* __restrict__ bv)
{
    extern __shared__ __align__(16) char smem[];
    const int z = blockIdx.z;
    const __nv_bfloat16* Bh = g_wth + (size_t)z * DIM * DIM;
    const __nv_bfloat16* Bl = g_wtl + (size_t)z * DIM * DIM;
    const float* bias = (z == 0) ? bq : (z == 1) ? bk : bv;
    __nv_bfloat16* Oh = (z == 0) ? g_qh : (z == 1) ? g_kh : g_vh;
    __nv_bfloat16* Ol = (z == 0) ? g_ql : (z == 1) ? g_kl : g_vl;
    const int m0 = blockIdx.y * 128, n0 = blockIdx.x * 128;

    float acc[4][4][4];
    mma_mainloop(g_xh + (size_t)m0 * DIM, g_xl + (size_t)m0 * DIM, DIM,
                 Bh + (size_t)n0 * DIM, Bl + (size_t)n0 * DIM, DIM, DIM, smem, acc);

    const int lane = threadIdx.x & 31, warp = threadIdx.x >> 5;
    const int wm = warp & 1, wn = warp >> 1;
#pragma unroll
    for (int mt = 0; mt < 4; mt++)
#pragma unroll
        for (int nt = 0; nt < 4; nt++) {
            const int r = m0 + wm * 64 + mt * 16 + (lane >> 2);
            const int c = n0 + wn * 32 + nt * 8 + (lane & 3) * 2;
            const float b0 = bias[c], b1 = bias[c + 1];
#pragma unroll
            for (int h = 0; h < 2; h++) {
                const int rr = r + h * 8;
                float v0 = acc[mt][nt][2 * h] + b0;
                float v1 = acc[mt][nt][2 * h + 1] + b1;
                __nv_bfloat16 h0 = __float2bfloat16(v0), h1 = __float2bfloat16(v1);
                const size_t o = (size_t)rr * DIM + c;
                *reinterpret_cast<uint32_t*>(Oh + o) = pack2(h0, h1);
                *reinterpret_cast<uint32_t*>(Ol + o) =
                    pack2(__float2bfloat16(v0 - __bfloat162float(h0)),
                          __float2bfloat16(v1 - __bfloat162float(h1)));
            }
        }
}

__global__ void __launch_bounds__(256, 2) scores_tc()
{
    extern __shared__ __align__(16) char smem[];
    const int b = blockIdx.z;
    const int m0 = blockIdx.y * 128, n0 = blockIdx.x * 128;
    const size_t qo = (size_t)b * SEQ * DIM;

    float acc[4][4][4];
    mma_mainloop(g_qh + qo + (size_t)m0 * DIM, g_ql + qo + (size_t)m0 * DIM, DIM,
                 g_kh + qo + (size_t)n0 * DIM, g_kl + qo + (size_t)n0 * DIM, DIM,
                 DIM, smem, acc);

    const int lane = threadIdx.x & 31, warp = threadIdx.x >> 5;
    const int wm = warp & 1, wn = warp >> 1;
    float* out = g_s + (size_t)b * SEQ * SEQ;
#pragma unroll
    for (int mt = 0; mt < 4; mt++)
#pragma unroll
        for (int nt = 0; nt < 4; nt++) {
            const int r = m0 + wm * 64 + mt * 16 + (lane >> 2);
            const int c = n0 + wn * 32 + nt * 8 + (lane & 3) * 2;
#pragma unroll
            for (int h = 0; h < 2; h++) {
                *reinterpret_cast<float2*>(out + (size_t)(r + h * 8) * SEQ + c) =
                    make_float2(acc[mt][nt][2 * h] * 0.03125f,
                                acc[mt][nt][2 * h + 1] * 0.03125f);
            }
        }
}

__global__ void __launch_bounds__(256, 2) ctx_tc(float* __restrict__ outp)
{
    extern __shared__ __align__(16) char smem[];
    const int b = blockIdx.z;
    const int m0 = blockIdx.y * 128, n0 = blockIdx.x * 128;
    const size_t po = (size_t)b * SEQ * SEQ;
    const size_t vo = (size_t)b * (size_t)DIM * SEQ;

    float acc[4][4][4];
    mma_mainloop(g_ph + po + (size_t)m0 * SEQ, g_pl + po + (size_t)m0 * SEQ, SEQ,
                 g_vth + vo + (size_t)n0 * SEQ, g_vtl + vo + (size_t)n0 * SEQ, SEQ,
                 SEQ, smem, acc);

    const int lane = threadIdx.x & 31, warp = threadIdx.x >> 5;
    const int wm = warp & 1, wn = warp >> 1;
    float* out = outp + (size_t)b * SEQ * DIM;
#pragma unroll
    for (int mt = 0; mt < 4; mt++)
#pragma unroll
        for (int nt = 0; nt < 4; nt++) {
            const int r = m0 + wm * 64 + mt * 16 + (lane >> 2);
            const int c = n0 + wn * 32 + nt * 8 + (lane & 3) * 2;
#pragma unroll
            for (int h = 0; h < 2; h++) {
                *reinterpret_cast<float2*>(out + (size_t)(r + h * 8) * DIM + c) =
                    make_float2(acc[mt][nt][2 * h], acc[mt][nt][2 * h + 1]);
            }
        }
}

// ===========================================================================
// Conversion / transpose / softmax / LN kernels
// ===========================================================================
__global__ void __launch_bounds__(256) conv_x(const float* __restrict__ x, int n4)
{
    int i = blockIdx.x * blockDim.x + threadIdx.x;
    if (i >= n4) return;
    float4 v = reinterpret_cast<const float4*>(x)[i];
    __nv_bfloat16 h0 = __float2bfloat16(v.x), h1 = __float2bfloat16(v.y);
    __nv_bfloat16 h2 = __float2bfloat16(v.z), h3 = __float2bfloat16(v.w);
    reinterpret_cast<uint2*>(g_xh)[i] = make_uint2(pack2(h0, h1), pack2(h2, h3));
    reinterpret_cast<uint2*>(g_xl)[i] = make_uint2(
        pack2(__float2bfloat16(v.x - __bfloat162float(h0)), __float2bfloat16(v.y - __bfloat162float(h1))),
        pack2(__float2bfloat16(v.z - __bfloat162float(h2)), __float2bfloat16(v.w - __bfloat162float(h3))));
}

__global__ void __launch_bounds__(256) conv_wT(
    const float* __restrict__ Wq, const float* __restrict__ Wk, const float* __restrict__ Wv)
{
    __shared__ float s[32][33];
    const float* W = (blockIdx.z == 0) ? Wq : (blockIdx.z == 1) ? Wk : Wv;
    __nv_bfloat16* oh = g_wth + (size_t)blockIdx.z * DIM * DIM;
    __nv_bfloat16* ol = g_wtl + (size_t)blockIdx.z * DIM * DIM;
    const int n0 = blockIdx.x * 32, k0 = blockIdx.y * 32;
    const int tx = threadIdx.x, ty = threadIdx.y;
#pragma unroll
    for (int i = 0; i < 32; i += 8)
        s[ty + i][tx] = W[(size_t)(k0 + ty + i) * DIM + n0 + tx];
    __syncthreads();
#pragma unroll
    for (int i = 0; i < 32; i += 8) {
        float v = s[tx][ty + i];
        __nv_bfloat16 h = __float2bfloat16(v);
        size_t o = (size_t)(n0 + ty + i) * DIM + k0 + tx;
        oh[o] = h;
        ol[o] = __float2bfloat16(v - __bfloat162float(h));
    }
}

__global__ void __launch_bounds__(256) transpose_v()
{
    __shared__ __nv_bfloat16 sh[32][33], sl[32][33];
    const int b = blockIdx.z;
    const int s0 = blockIdx.x * 32, d0 = blockIdx.y * 32;
    const int tx = threadIdx.x, ty = threadIdx.y;
    const __nv_bfloat16* Vh = g_vh + (size_t)b * SEQ * DIM;
    const __nv_bfloat16* Vl = g_vl + (size_t)b * SEQ * DIM;
    __nv_bfloat16* Th = g_vth + (size_t)b * (size_t)DIM * SEQ;
    __nv_bfloat16* Tl = g_vtl + (size_t)b * (size_t)DIM * SEQ;
#pragma unroll
    for (int i = 0; i < 32; i += 8) {
        sh[ty + i][tx] = Vh[(size_t)(s0 + ty + i) * DIM + d0 + tx];
        sl[ty + i][tx] = Vl[(size_t)(s0 + ty + i) * DIM + d0 + tx];
    }
    __syncthreads();
#pragma unroll
    for (int i = 0; i < 32; i += 8) {
        size_t o = (size_t)(d0 + ty + i) * SEQ + s0 + tx;
        Th[o] = sh[tx][ty + i];
        Tl[o] = sl[tx][ty + i];
    }
}

__global__ void __launch_bounds__(256) softmax_split()
{
    __shared__ float red[256];
    const int t = threadIdx.x;
    const float* p = g_s + (size_t)blockIdx.x * SEQ;

    float4 v0 = reinterpret_cast<const float4*>(p)[t];
    float4 v1 = reinterpret_cast<const float4*>(p)[t + 256];

    float mx = fmaxf(fmaxf(fmaxf(v0.x, v0.y), fmaxf(v0.z, v0.w)),
                     fmaxf(fmaxf(v1.x, v1.y), fmaxf(v1.z, v1.w)));
    red[t] = mx;
    __syncthreads();
#pragma unroll
    for (int o = 128; o > 0; o >>= 1) {
        if (t < o) red[t] = fmaxf(red[t], red[t + o]);
        __syncthreads();
    }
    mx = red[0];
    __syncthreads();

    v0.x = __expf(v0.x - mx); v0.y = __expf(v0.y - mx);
    v0.z = __expf(v0.z - mx); v0.w = __expf(v0.w - mx);
    v1.x = __expf(v1.x - mx); v1.y = __expf(v1.y - mx);
    v1.z = __expf(v1.z - mx); v1.w = __expf(v1.w - mx);

    red[t] = (v0.x + v0.y) + (v0.z + v0.w) + (v1.x + v1.y) + (v1.z + v1.w);
    __syncthreads();
#pragma unroll
    for (int o = 128; o > 0; o >>= 1) {
        if (t < o) red[t] += red[t + o];
        __syncthreads();
    }
    const float inv = 1.0f / red[0];

    float a[8] = {v0.x * inv, v0.y * inv, v0.z * inv, v0.w * inv,
                  v1.x * inv, v1.y * inv, v1.z * inv, v1.w * inv};
    __nv_bfloat16 h[8];
    uint32_t hw[4], lw[4];
#pragma unroll
    for (int j = 0; j < 8; j++) h[j] = __float2bfloat16(a[j]);
#pragma unroll
    for (int j = 0; j < 4; j++) {
        hw[j] = pack2(h[2 * j], h[2 * j + 1]);
        lw[j] = pack2(__float2bfloat16(a[2 * j]     - __bfloat162float(h[2 * j])),
                      __float2bfloat16(a[2 * j + 1] - __bfloat162float(h[2 * j + 1])));
    }
    __nv_bfloat16* ph = g_ph + (size_t)blockIdx.x * SEQ;
    __nv_bfloat16* pl = g_pl + (size_t)blockIdx.x * SEQ;
    reinterpret_cast<uint2*>(ph)[t]        = make_uint2(hw[0], hw[1]);
    reinterpret_cast<uint2*>(ph + 1024)[t] = make_uint2(hw[2], hw[3]);
    reinterpret_cast<uint2*>(pl)[t]        = make_uint2(lw[0], lw[1]);
    reinterpret_cast<uint2*>(pl + 1024)[t] = make_uint2(lw[2], lw[3]);
}

__global__ void __launch_bounds__(256) ln_kernel(
    const float* __restrict__ x, const float* __restrict__ gamma,
    const float* __restrict__ beta, float* __restrict__ io)
{
    __shared__ float red[256];
    const int t = threadIdx.x;
    const size_t base = (size_t)blockIdx.x * DIM;

    float4 c  = reinterpret_cast<const float4*>(io + base)[t];
    float4 xi = reinterpret_cast<const float4*>(x + base)[t];
    float4 r  = make_float4(c.x + xi.x, c.y + xi.y, c.z + xi.z, c.w + xi.w);

    red[t] = (r.x + r.y) + (r.z + r.w);
    __syncthreads();
#pragma unroll
    for (int o = 128; o > 0; o >>= 1) {
        if (t < o) red[t] += red[t + o];
        __syncthreads();
    }
    const float mu = red[0] * (1.0f / DIM);
    __syncthreads();

    float4 d = make_float4(r.x - mu, r.y - mu, r.z - mu, r.w - mu);
    red[t] = (d.x * d.x + d.y * d.y) + (d.z * d.z + d.w * d.w);
    __syncthreads();
#pragma unroll
    for (int o = 128; o > 0; o >>= 1) {
        if (t < o) red[t] += red[t + o];
        __syncthreads();
    }
    const float var = red[0] * (1.0f / DIM);
    const float w = rsqrtf(var + 1e-3f);

    float4 g  = reinterpret_cast<const float4*>(gamma)[t];
    float4 bt = reinterpret_cast<const float4*>(beta)[t];
    reinterpret_cast<float4*>(io + base)[t] =
        make_float4(d.x * w * g.x + bt.x, d.y * w * g.y + bt.y,
                    d.z * w * g.z + bt.z, d.w * w * g.w + bt.w);
}

// ===========================================================================
// Launch
// ===========================================================================
extern "C" void kernel_launch(void* const* d_in, const int* in_sizes, int n_in,
                              void* d_out, int out_size)
{
    const float* X  = (const float*)d_in[0];
    const float* Wq = (const float*)d_in[1];
    const float* bq = (const float*)d_in[2];
    const float* Wk = (const float*)d_in[3];
    const float* bk = (const float*)d_in[4];
    const float* Wv = (const float*)d_in[5];
    const float* bv = (const float*)d_in[6];
    const float* gm = (const float*)d_in[7];
    const float* bt = (const float*)d_in[8];
    float* out = (float*)d_out;

    cudaFuncSetAttribute(qkv_tc,    cudaFuncAttributeMaxDynamicSharedMemorySize, SMEM_GEMM_BYTES);
    cudaFuncSetAttribute(scores_tc, cudaFuncAttributeMaxDynamicSharedMemorySize, SMEM_GEMM_BYTES);
    cudaFuncSetAttribute(ctx_tc,    cudaFuncAttributeMaxDynamicSharedMemorySize, SMEM_GEMM_BYTES);

    // split X into bf16 hi/lo
    conv_x<<<(MROWS * DIM / 4 + 255) / 256, 256>>>(X, MROWS * DIM / 4);
    // transpose + split weights -> [n][k]
    conv_wT<<<dim3(32, 32, 3), dim3(32, 8)>>>(Wq, Wk, Wv);
    // Q/K/V projections (tensor cores), outputs split bf16
    qkv_tc<<<dim3(DIM / 128, MROWS / 128, 3), 256, SMEM_GEMM_BYTES>>>(bq, bk, bv);
    // V^T per batch for context GEMM B operand
    transpose_v<<<dim3(SEQ / 32, DIM / 32, BATCH), dim3(32, 8)>>>();
    // scores = Q K^T / 32
    scores_tc<<<dim3(SEQ / 128, SEQ / 128, BATCH), 256, SMEM_GEMM_BYTES>>>();
    // softmax + split to bf16 hi/lo
    softmax_split<<<MROWS, 256>>>();
    // context = P V  -> d_out (fp32)
    ctx_tc<<<dim3(DIM / 128, SEQ / 128, BATCH), 256, SMEM_GEMM_BYTES>>>(out);
    // residual + layernorm in place on d_out
    ln_kernel<<<MROWS, 256>>>(X, gm, bt, out);
}

// round 5
// speedup vs baseline: 1.1185x; 1.1185x over previous
#include <cuda_runtime.h>
#include <cuda_bf16.h>
#include <cstdint>

// Problem dims
#define BATCH 4
#define SEQ   2048
#define DIM   1024
#define MROWS (BATCH * SEQ)   // 8192

// ===========================================================================
// Scratch (device globals; no allocation allowed anywhere)
// ===========================================================================
__device__ __align__(16) __nv_bfloat16 g_xh[(size_t)MROWS * DIM];
__device__ __align__(16) __nv_bfloat16 g_xl[(size_t)MROWS * DIM];
__device__ __align__(16) __nv_bfloat16 g_wth[(size_t)3 * DIM * DIM];  // W^T hi [n][k]
__device__ __align__(16) __nv_bfloat16 g_wtl[(size_t)3 * DIM * DIM];  // W^T lo
__device__ __align__(16) __nv_bfloat16 g_qh[(size_t)MROWS * DIM];
__device__ __align__(16) __nv_bfloat16 g_ql[(size_t)MROWS * DIM];
__device__ __align__(16) __nv_bfloat16 g_kh[(size_t)MROWS * DIM];
__device__ __align__(16) __nv_bfloat16 g_kl[(size_t)MROWS * DIM];
__device__ __align__(16) __nv_bfloat16 g_vh[(size_t)MROWS * DIM];
__device__ __align__(16) __nv_bfloat16 g_vl[(size_t)MROWS * DIM];
__device__ __align__(16) __nv_bfloat16 g_vth[(size_t)MROWS * DIM];   // V^T per batch [D][S]
__device__ __align__(16) __nv_bfloat16 g_vtl[(size_t)MROWS * DIM];
__device__ __align__(16) float         g_s[(size_t)BATCH * SEQ * SEQ];
__device__ __align__(16) __nv_bfloat16 g_ph[(size_t)BATCH * SEQ * SEQ];
__device__ __align__(16) __nv_bfloat16 g_pl[(size_t)BATCH * SEQ * SEQ];

// ===========================================================================
// Baseline-ISA warp MMA helpers (sm_80+: mma.sync / ldmatrix / cp.async)
// ===========================================================================
__device__ __forceinline__ uint32_t smem_u32(const void* p) {
    uint32_t a;
    asm("{ .reg .u64 t; cvta.to.shared.u64 t, %1; cvt.u32.u64 %0, t; }" : "=r"(a) : "l"(p));
    return a;
}

__device__ __forceinline__ void ldsm_x4(uint32_t& r0, uint32_t& r1, uint32_t& r2, uint32_t& r3,
                                        uint32_t addr) {
    asm volatile("ldmatrix.sync.aligned.m8n8.x4.shared.b16 {%0,%1,%2,%3}, [%4];"
                 : "=r"(r0), "=r"(r1), "=r"(r2), "=r"(r3) : "r"(addr));
}

__device__ __forceinline__ void mma16816(float* c, const uint32_t* a, const uint32_t* b) {
    asm volatile(
        "mma.sync.aligned.m16n8k16.row.col.f32.bf16.bf16.f32 "
        "{%0,%1,%2,%3}, {%4,%5,%6,%7}, {%8,%9}, {%0,%1,%2,%3};"
        : "+f"(c[0]), "+f"(c[1]), "+f"(c[2]), "+f"(c[3])
        : "r"(a[0]), "r"(a[1]), "r"(a[2]), "r"(a[3]), "r"(b[0]), "r"(b[1]));
}

__device__ __forceinline__ void cp_async16(uint32_t saddr, const void* gaddr) {
    asm volatile("cp.async.cg.shared.global [%0], [%1], 16;" :: "r"(saddr), "l"(gaddr));
}
__device__ __forceinline__ void cp_commit() { asm volatile("cp.async.commit_group;"); }
template <int N> __device__ __forceinline__ void cp_wait() {
    asm volatile("cp.async.wait_group %0;" :: "n"(N));
}

__device__ __forceinline__ uint32_t pack2(__nv_bfloat16 a, __nv_bfloat16 b) {
    __nv_bfloat162 p; p.x = a; p.y = b;
    return *reinterpret_cast<uint32_t*>(&p);
}

// ===========================================================================
// GEMM mainloop: acc[4][4][4] += (Ah+Al)[128,K] @ (Bh+Bl)[128,K]^T  (bf16x3)
//   A row-major [M,K] hi/lo, B row-major [N,K] hi/lo (i.e. C = A @ B^T).
//   CTA tile 128x128, K-chunk 32, 256 threads = 8 warps (2 M x 4 N),
//   warp tile 64x32. Smem: 2 stages x 4 tiles x [128 rows x 80B] (pad 64->80).
//   Phase-ordered MMAs: 16 independent MMAs per phase (no RAW chains).
// ===========================================================================
#define ROW_B   80          // padded row bytes (32 bf16 = 64B data + 16B pad)
#define TILE_B  (128 * ROW_B)   // 10240
#define STAGE_B (4 * TILE_B)    // 40960
#define SMEM_GEMM_BYTES (2 * STAGE_B)  // 81920

// copy one 128x32 bf16 tile (row stride ld elems) into padded smem (this
// thread's 2 of 512 16B-chunks)
__device__ __forceinline__ void cpa_tile(const __nv_bfloat16* __restrict__ g, int ld,
                                         uint32_t sdst, int t) {
#pragma unroll
    for (int h = 0; h < 2; h++) {
        const int c   = t + h * 256;       // chunk id 0..511
        const int row = c >> 2;
        const int col = c & 3;             // 16B unit in row
        const char* gp = reinterpret_cast<const char*>(g) + (size_t)row * ld * 2 + col * 16;
        cp_async16(sdst + row * ROW_B + col * 16, gp);
    }
}

__device__ __forceinline__ void load_stage(
    const __nv_bfloat16* Ah, const __nv_bfloat16* Al, int lda,
    const __nv_bfloat16* Bh, const __nv_bfloat16* Bl, int ldb,
    int stg, uint32_t sbase, int buf, int t)
{
    const size_t ko = (size_t)stg * 32;
    const uint32_t st = sbase + buf * STAGE_B;
    cpa_tile(Ah + ko, lda, st + 0 * TILE_B, t);
    cpa_tile(Al + ko, lda, st + 1 * TILE_B, t);
    cpa_tile(Bh + ko, ldb, st + 2 * TILE_B, t);
    cpa_tile(Bl + ko, ldb, st + 3 * TILE_B, t);
    cp_commit();
}

__device__ __forceinline__ void mma_mainloop(
    const __nv_bfloat16* __restrict__ Ah, const __nv_bfloat16* __restrict__ Al, int lda,
    const __nv_bfloat16* __restrict__ Bh, const __nv_bfloat16* __restrict__ Bl, int ldb,
    int Kdim, char* smem, float acc[4][4][4])
{
    const int t    = threadIdx.x;
    const int lane = t & 31;
    const int warp = t >> 5;
    const int wm   = warp & 1;   // 0..1  (64-row block)
    const int wn   = warp >> 1;  // 0..3  (32-col block)
    const uint32_t sbase = smem_u32(smem);

    // ldmatrix per-lane offsets (canonical m16n8k16 mappings)
    const int aRow = lane & 15;
    const int aK   = (lane >> 4) & 1;              // k-half select
    const int bRow = (lane & 7) | (((lane >> 4) & 1) << 3);
    const int bK   = (lane >> 3) & 1;

    const uint32_t aBase = (wm * 64 + aRow) * ROW_B + aK * 16;
    const uint32_t bBase = (wn * 32 + bRow) * ROW_B + bK * 16;

#pragma unroll
    for (int i = 0; i < 4; i++)
#pragma unroll
        for (int j = 0; j < 4; j++)
#pragma unroll
            for (int q = 0; q < 4; q++) acc[i][j][q] = 0.0f;

    const int nstg = Kdim >> 5;
    load_stage(Ah, Al, lda, Bh, Bl, ldb, 0, sbase, 0, t);

    for (int i = 0; i < nstg; i++) {
        const int buf = i & 1;
        const bool more = (i + 1 < nstg);
        if (more) load_stage(Ah, Al, lda, Bh, Bl, ldb, i + 1, sbase, buf ^ 1, t);
        if (more) cp_wait<1>(); else cp_wait<0>();
        __syncthreads();

        const uint32_t st  = sbase + buf * STAGE_B;
        const uint32_t AhT = st, AlT = st + TILE_B, BhT = st + 2 * TILE_B, BlT = st + 3 * TILE_B;

#pragma unroll
        for (int step = 0; step < 2; step++) {
            const uint32_t ao = aBase + step * 32;
            const uint32_t bo = bBase + step * 32;

            // Phase 1: ah, bh -> 16 independent hh MMAs
            uint32_t ah[4][4], bh[4][2];
#pragma unroll
            for (int mt = 0; mt < 4; mt++)
                ldsm_x4(ah[mt][0], ah[mt][1], ah[mt][2], ah[mt][3], AhT + ao + mt * 16 * ROW_B);
#pragma unroll
            for (int g = 0; g < 2; g++) {
                uint32_t r0, r1, r2, r3;
                ldsm_x4(r0, r1, r2, r3, BhT + bo + g * 16 * ROW_B);
                bh[2 * g][0] = r0;     bh[2 * g][1] = r1;
                bh[2 * g + 1][0] = r2; bh[2 * g + 1][1] = r3;
            }
#pragma unroll
            for (int mt = 0; mt < 4; mt++)
#pragma unroll
                for (int nt = 0; nt < 4; nt++) mma16816(acc[mt][nt], ah[mt], bh[nt]);

            // Phase 2: bl -> 16 independent hl MMAs
            {
                uint32_t bl[4][2];
#pragma unroll
                for (int g = 0; g < 2; g++) {
                    uint32_t r0, r1, r2, r3;
                    ldsm_x4(r0, r1, r2, r3, BlT + bo + g * 16 * ROW_B);
                    bl[2 * g][0] = r0;     bl[2 * g][1] = r1;
                    bl[2 * g + 1][0] = r2; bl[2 * g + 1][1] = r3;
                }
#pragma unroll
                for (int mt = 0; mt < 4; mt++)
#pragma unroll
                    for (int nt = 0; nt < 4; nt++) mma16816(acc[mt][nt], ah[mt], bl[nt]);
            }

            // Phase 3: al -> 16 independent lh MMAs
            {
                uint32_t al[4][4];
#pragma unroll
                for (int mt = 0; mt < 4; mt++)
                    ldsm_x4(al[mt][0], al[mt][1], al[mt][2], al[mt][3], AlT + ao + mt * 16 * ROW_B);
#pragma unroll
                for (int mt = 0; mt < 4; mt++)
#pragma unroll
                    for (int nt = 0; nt < 4; nt++) mma16816(acc[mt][nt], al[mt], bh[nt]);
            }
        }
        __syncthreads();
    }
}

// acc element coords: tile (mt,nt): r = wm*64 + mt*16 + lane/4 (+8 for c2,c3)
//                     c = wn*32 + nt*8 + (lane%4)*2 (+1 for odd)
// ===========================================================================
// GEMM kernels
// ===========================================================================
__global__ void __launch_bounds__(256, 2) qkv_tc(
    const float* __restrict__ bq, const float* __restrict__ bk, const float* __restrict__ bv)
{
    extern __shared__ __align__(16) char smem[];
    const int z = blockIdx.z;
    const __nv_bfloat16* Bh = g_wth + (size_t)z * DIM * DIM;
    const __nv_bfloat16* Bl = g_wtl + (size_t)z * DIM * DIM;
    const float* bias = (z == 0) ? bq : (z == 1) ? bk : bv;
    __nv_bfloat16* Oh = (z == 0) ? g_qh : (z == 1) ? g_kh : g_vh;
    __nv_bfloat16* Ol = (z == 0) ? g_ql : (z == 1) ? g_kl : g_vl;
    const int m0 = blockIdx.y * 128, n0 = blockIdx.x * 128;

    float acc[4][4][4];
    mma_mainloop(g_xh + (size_t)m0 * DIM, g_xl + (size_t)m0 * DIM, DIM,
                 Bh + (size_t)n0 * DIM, Bl + (size_t)n0 * DIM, DIM, DIM, smem, acc);

    const int lane = threadIdx.x & 31, warp = threadIdx.x >> 5;
    const int wm = warp & 1, wn = warp >> 1;
#pragma unroll
    for (int mt = 0; mt < 4; mt++)
#pragma unroll
        for (int nt = 0; nt < 4; nt++) {
            const int r = m0 + wm * 64 + mt * 16 + (lane >> 2);
            const int c = n0 + wn * 32 + nt * 8 + (lane & 3) * 2;
            const float b0 = bias[c], b1 = bias[c + 1];
#pragma unroll
            for (int h = 0; h < 2; h++) {
                const int rr = r + h * 8;
                float v0 = acc[mt][nt][2 * h] + b0;
                float v1 = acc[mt][nt][2 * h + 1] + b1;
                __nv_bfloat16 h0 = __float2bfloat16(v0), h1 = __float2bfloat16(v1);
                const size_t o = (size_t)rr * DIM + c;
                *reinterpret_cast<uint32_t*>(Oh + o) = pack2(h0, h1);
                *reinterpret_cast<uint32_t*>(Ol + o) =
                    pack2(__float2bfloat16(v0 - __bfloat162float(h0)),
                          __float2bfloat16(v1 - __bfloat162float(h1)));
            }
        }
}

__global__ void __launch_bounds__(256, 2) scores_tc()
{
    extern __shared__ __align__(16) char smem[];
    const int b = blockIdx.z;
    const int m0 = blockIdx.y * 128, n0 = blockIdx.x * 128;
    const size_t qo = (size_t)b * SEQ * DIM;

    float acc[4][4][4];
    mma_mainloop(g_qh + qo + (size_t)m0 * DIM, g_ql + qo + (size_t)m0 * DIM, DIM,
                 g_kh + qo + (size_t)n0 * DIM, g_kl + qo + (size_t)n0 * DIM, DIM,
                 DIM, smem, acc);

    const int lane = threadIdx.x & 31, warp = threadIdx.x >> 5;
    const int wm = warp & 1, wn = warp >> 1;
    float* out = g_s + (size_t)b * SEQ * SEQ;
#pragma unroll
    for (int mt = 0; mt < 4; mt++)
#pragma unroll
        for (int nt = 0; nt < 4; nt++) {
            const int r = m0 + wm * 64 + mt * 16 + (lane >> 2);
            const int c = n0 + wn * 32 + nt * 8 + (lane & 3) * 2;
#pragma unroll
            for (int h = 0; h < 2; h++) {
                *reinterpret_cast<float2*>(out + (size_t)(r + h * 8) * SEQ + c) =
                    make_float2(acc[mt][nt][2 * h] * 0.03125f,
                                acc[mt][nt][2 * h + 1] * 0.03125f);
            }
        }
}

__global__ void __launch_bounds__(256, 2) ctx_tc(float* __restrict__ outp)
{
    extern __shared__ __align__(16) char smem[];
    const int b = blockIdx.z;
    const int m0 = blockIdx.y * 128, n0 = blockIdx.x * 128;
    const size_t po = (size_t)b * SEQ * SEQ;
    const size_t vo = (size_t)b * (size_t)DIM * SEQ;

    float acc[4][4][4];
    mma_mainloop(g_ph + po + (size_t)m0 * SEQ, g_pl + po + (size_t)m0 * SEQ, SEQ,
                 g_vth + vo + (size_t)n0 * SEQ, g_vtl + vo + (size_t)n0 * SEQ, SEQ,
                 SEQ, smem, acc);

    const int lane = threadIdx.x & 31, warp = threadIdx.x >> 5;
    const int wm = warp & 1, wn = warp >> 1;
    float* out = outp + (size_t)b * SEQ * DIM;
#pragma unroll
    for (int mt = 0; mt < 4; mt++)
#pragma unroll
        for (int nt = 0; nt < 4; nt++) {
            const int r = m0 + wm * 64 + mt * 16 + (lane >> 2);
            const int c = n0 + wn * 32 + nt * 8 + (lane & 3) * 2;
#pragma unroll
            for (int h = 0; h < 2; h++) {
                *reinterpret_cast<float2*>(out + (size_t)(r + h * 8) * DIM + c) =
                    make_float2(acc[mt][nt][2 * h], acc[mt][nt][2 * h + 1]);
            }
        }
}

// ===========================================================================
// Conversion / transpose / softmax / LN kernels
// ===========================================================================
__global__ void __launch_bounds__(256) conv_x(const float* __restrict__ x, int n4)
{
    int i = blockIdx.x * blockDim.x + threadIdx.x;
    if (i >= n4) return;
    float4 v = reinterpret_cast<const float4*>(x)[i];
    __nv_bfloat16 h0 = __float2bfloat16(v.x), h1 = __float2bfloat16(v.y);
    __nv_bfloat16 h2 = __float2bfloat16(v.z), h3 = __float2bfloat16(v.w);
    reinterpret_cast<uint2*>(g_xh)[i] = make_uint2(pack2(h0, h1), pack2(h2, h3));
    reinterpret_cast<uint2*>(g_xl)[i] = make_uint2(
        pack2(__float2bfloat16(v.x - __bfloat162float(h0)), __float2bfloat16(v.y - __bfloat162float(h1))),
        pack2(__float2bfloat16(v.z - __bfloat162float(h2)), __float2bfloat16(v.w - __bfloat162float(h3))));
}

__global__ void __launch_bounds__(256) conv_wT(
    const float* __restrict__ Wq, const float* __restrict__ Wk, const float* __restrict__ Wv)
{
    __shared__ float s[32][33];
    const float* W = (blockIdx.z == 0) ? Wq : (blockIdx.z == 1) ? Wk : Wv;
    __nv_bfloat16* oh = g_wth + (size_t)blockIdx.z * DIM * DIM;
    __nv_bfloat16* ol = g_wtl + (size_t)blockIdx.z * DIM * DIM;
    const int n0 = blockIdx.x * 32, k0 = blockIdx.y * 32;
    const int tx = threadIdx.x, ty = threadIdx.y;
#pragma unroll
    for (int i = 0; i < 32; i += 8)
        s[ty + i][tx] = W[(size_t)(k0 + ty + i) * DIM + n0 + tx];
    __syncthreads();
#pragma unroll
    for (int i = 0; i < 32; i += 8) {
        float v = s[tx][ty + i];
        __nv_bfloat16 h = __float2bfloat16(v);
        size_t o = (size_t)(n0 + ty + i) * DIM + k0 + tx;
        oh[o] = h;
        ol[o] = __float2bfloat16(v - __bfloat162float(h));
    }
}

__global__ void __launch_bounds__(256) transpose_v()
{
    __shared__ __nv_bfloat16 sh[32][33], sl[32][33];
    const int b = blockIdx.z;
    const int s0 = blockIdx.x * 32, d0 = blockIdx.y * 32;
    const int tx = threadIdx.x, ty = threadIdx.y;
    const __nv_bfloat16* Vh = g_vh + (size_t)b * SEQ * DIM;
    const __nv_bfloat16* Vl = g_vl + (size_t)b * SEQ * DIM;
    __nv_bfloat16* Th = g_vth + (size_t)b * (size_t)DIM * SEQ;
    __nv_bfloat16* Tl = g_vtl + (size_t)b * (size_t)DIM * SEQ;
#pragma unroll
    for (int i = 0; i < 32; i += 8) {
        sh[ty + i][tx] = Vh[(size_t)(s0 + ty + i) * DIM + d0 + tx];
        sl[ty + i][tx] = Vl[(size_t)(s0 + ty + i) * DIM + d0 + tx];
    }
    __syncthreads();
#pragma unroll
    for (int i = 0; i < 32; i += 8) {
        size_t o = (size_t)(d0 + ty + i) * SEQ + s0 + tx;
        Th[o] = sh[tx][ty + i];
        Tl[o] = sl[tx][ty + i];
    }
}

__global__ void __launch_bounds__(256) softmax_split()
{
    __shared__ float red[256];
    const int t = threadIdx.x;
    const float* p = g_s + (size_t)blockIdx.x * SEQ;

    float4 v0 = reinterpret_cast<const float4*>(p)[t];
    float4 v1 = reinterpret_cast<const float4*>(p)[t + 256];

    float mx = fmaxf(fmaxf(fmaxf(v0.x, v0.y), fmaxf(v0.z, v0.w)),
                     fmaxf(fmaxf(v1.x, v1.y), fmaxf(v1.z, v1.w)));
    red[t] = mx;
    __syncthreads();
#pragma unroll
    for (int o = 128; o > 0; o >>= 1) {
        if (t < o) red[t] = fmaxf(red[t], red[t + o]);
        __syncthreads();
    }
    mx = red[0];
    __syncthreads();

    v0.x = __expf(v0.x - mx); v0.y = __expf(v0.y - mx);
    v0.z = __expf(v0.z - mx); v0.w = __expf(v0.w - mx);
    v1.x = __expf(v1.x - mx); v1.y = __expf(v1.y - mx);
    v1.z = __expf(v1.z - mx); v1.w = __expf(v1.w - mx);

    red[t] = (v0.x + v0.y) + (v0.z + v0.w) + (v1.x + v1.y) + (v1.z + v1.w);
    __syncthreads();
#pragma unroll
    for (int o = 128; o > 0; o >>= 1) {
        if (t < o) red[t] += red[t + o];
        __syncthreads();
    }
    const float inv = 1.0f / red[0];

    float a[8] = {v0.x * inv, v0.y * inv, v0.z * inv, v0.w * inv,
                  v1.x * inv, v1.y * inv, v1.z * inv, v1.w * inv};
    __nv_bfloat16 h[8];
    uint32_t hw[4], lw[4];
#pragma unroll
    for (int j = 0; j < 8; j++) h[j] = __float2bfloat16(a[j]);
#pragma unroll
    for (int j = 0; j < 4; j++) {
        hw[j] = pack2(h[2 * j], h[2 * j + 1]);
        lw[j] = pack2(__float2bfloat16(a[2 * j]     - __bfloat162float(h[2 * j])),
                      __float2bfloat16(a[2 * j + 1] - __bfloat162float(h[2 * j + 1])));
    }
    __nv_bfloat16* ph = g_ph + (size_t)blockIdx.x * SEQ;
    __nv_bfloat16* pl = g_pl + (size_t)blockIdx.x * SEQ;
    reinterpret_cast<uint2*>(ph)[t]        = make_uint2(hw[0], hw[1]);
    reinterpret_cast<uint2*>(ph + 1024)[t] = make_uint2(hw[2], hw[3]);
    reinterpret_cast<uint2*>(pl)[t]        = make_uint2(lw[0], lw[1]);
    reinterpret_cast<uint2*>(pl + 1024)[t] = make_uint2(lw[2], lw[3]);
}

__global__ void __launch_bounds__(256) ln_kernel(
    const float* __restrict__ x, const float* __restrict__ gamma,
    const float* __restrict__ beta, float* __restrict__ io)
{
    __shared__ float red[256];
    const int t = threadIdx.x;
    const size_t base = (size_t)blockIdx.x * DIM;

    float4 c  = reinterpret_cast<const float4*>(io + base)[t];
    float4 xi = reinterpret_cast<const float4*>(x + base)[t];
    float4 r  = make_float4(c.x + xi.x, c.y + xi.y, c.z + xi.z, c.w + xi.w);

    red[t] = (r.x + r.y) + (r.z + r.w);
    __syncthreads();
#pragma unroll
    for (int o = 128; o > 0; o >>= 1) {
        if (t < o) red[t] += red[t + o];
        __syncthreads();
    }
    const float mu = red[0] * (1.0f / DIM);
    __syncthreads();

    float4 d = make_float4(r.x - mu, r.y - mu, r.z - mu, r.w - mu);
    red[t] = (d.x * d.x + d.y * d.y) + (d.z * d.z + d.w * d.w);
    __syncthreads();
#pragma unroll
    for (int o = 128; o > 0; o >>= 1) {
        if (t < o) red[t] += red[t + o];
        __syncthreads();
    }
    const float var = red[0] * (1.0f / DIM);
    const float w = rsqrtf(var + 1e-3f);

    float4 g  = reinterpret_cast<const float4*>(gamma)[t];
    float4 bt = reinterpret_cast<const float4*>(beta)[t];
    reinterpret_cast<float4*>(io + base)[t] =
        make_float4(d.x * w * g.x + bt.x, d.y * w * g.y + bt.y,
                    d.z * w * g.z + bt.z, d.w * w * g.w + bt.w);
}

// ===========================================================================
// Launch
// ===========================================================================
extern "C" void kernel_launch(void* const* d_in, const int* in_sizes, int n_in,
                              void* d_out, int out_size)
{
    const float* X  = (const float*)d_in[0];
    const float* Wq = (const float*)d_in[1];
    const float* bq = (const float*)d_in[2];
    const float* Wk = (const float*)d_in[3];
    const float* bk = (const float*)d_in[4];
    const float* Wv = (const float*)d_in[5];
    const float* bv = (const float*)d_in[6];
    const float* gm = (const float*)d_in[7];
    const float* bt = (const float*)d_in[8];
    float* out = (float*)d_out;

    cudaFuncSetAttribute(qkv_tc,    cudaFuncAttributeMaxDynamicSharedMemorySize, SMEM_GEMM_BYTES);
    cudaFuncSetAttribute(scores_tc, cudaFuncAttributeMaxDynamicSharedMemorySize, SMEM_GEMM_BYTES);
    cudaFuncSetAttribute(ctx_tc,    cudaFuncAttributeMaxDynamicSharedMemorySize, SMEM_GEMM_BYTES);

    // split X into bf16 hi/lo
    conv_x<<<(MROWS * DIM / 4 + 255) / 256, 256>>>(X, MROWS * DIM / 4);
    // transpose + split weights -> [n][k]
    conv_wT<<<dim3(32, 32, 3), dim3(32, 8)>>>(Wq, Wk, Wv);
    // Q/K/V projections (tensor cores), outputs split bf16
    qkv_tc<<<dim3(DIM / 128, MROWS / 128, 3), 256, SMEM_GEMM_BYTES>>>(bq, bk, bv);
    // V^T per batch for context GEMM B operand
    transpose_v<<<dim3(SEQ / 32, DIM / 32, BATCH), dim3(32, 8)>>>();
    // scores = Q K^T / 32
    scores_tc<<<dim3(SEQ / 128, SEQ / 128, BATCH), 256, SMEM_GEMM_BYTES>>>();
    // softmax + split to bf16 hi/lo
    softmax_split<<<MROWS, 256>>>();
    // context = P V  -> d_out (fp32)
    ctx_tc<<<dim3(DIM / 128, SEQ / 128, BATCH), 256, SMEM_GEMM_BYTES>>>(out);
    // residual + layernorm in place on d_out
    ln_kernel<<<MROWS, 256>>>(X, gm, bt, out);
}